// round 9
// baseline (speedup 1.0000x reference)
#include <cuda_runtime.h>
#include <cstdint>
#include <cstddef>

#define BATCH 128
#define SEQT  1024
#define VD    256
#define TPB   256
#define TPBR  512

// ---------------- device scratch (static, no allocation) ----------------
__device__ float g_xp[134217728];                       // x_proj permuted [T][cg8][g4][b128][col32]
__device__ float g_h1s[BATCH * SEQT * VD];              // layer-1 hidden states [B,T,V]
__device__ float g_h2s[BATCH * SEQT * VD];              // layer-2 hidden states [B,T,V]
__device__ __align__(128) float g_hbuf[2 * BATCH * VD]; // double-buffered h exchange
__device__ float g_wn[VD * VD];                         // row-normalized fc weight
// per-group flag barrier: 16 groups x 8 CTA flags (first 32B of a 128B line)
__device__ __align__(128) unsigned g_flag[16 * 32];

// ---------------- packed f32x2 helpers ----------------
__device__ __forceinline__ float2 fma2(float2 acc, float2 w, float2 v) {
    unsigned long long ua, uw, uv;
    ua = *reinterpret_cast<unsigned long long*>(&acc);
    uw = *reinterpret_cast<unsigned long long*>(&w);
    uv = *reinterpret_cast<unsigned long long*>(&v);
    asm("fma.rn.f32x2 %0, %1, %2, %0;" : "+l"(ua) : "l"(uw), "l"(uv));
    return *reinterpret_cast<float2*>(&ua);
}

__device__ __forceinline__ float2 add2(float2 a, float2 b) {
    unsigned long long ua, ub;
    ua = *reinterpret_cast<unsigned long long*>(&a);
    ub = *reinterpret_cast<unsigned long long*>(&b);
    asm("add.rn.f32x2 %0, %0, %1;" : "+l"(ua) : "l"(ub));
    return *reinterpret_cast<float2*>(&ua);
}

__device__ __forceinline__ float2 shfl_xor2(float2 v, int m) {
    unsigned long long u = *reinterpret_cast<unsigned long long*>(&v);
    u = __shfl_xor_sync(0xffffffffu, u, m);
    return *reinterpret_cast<float2*>(&u);
}

__device__ __forceinline__ float sigmoidf_(float x) {
    return 1.0f / (1.0f + __expf(-x));
}

__device__ __forceinline__ unsigned ld_acq(const unsigned* p) {
    unsigned v;
    asm volatile("ld.acquire.gpu.global.u32 %0, [%1];" : "=r"(v) : "l"(p) : "memory");
    return v;
}

// =======================================================================
// GEMM: x_proj[m][n] = A[m][0:256] . W[n][0:256] + bih[n] + bhh[n]
// Output PERMUTED into g_xp: [t][cg(8)][g(4)][b(128)][col(32)]
// =======================================================================
#define GBK 16

__global__ void __launch_bounds__(256)
gemm_xproj(const float* __restrict__ A, const float* __restrict__ W,
           const float* __restrict__ bih, const float* __restrict__ bhh) {
    __shared__ float As[2][GBK][132];
    __shared__ float Bs[2][GBK][68];

    const int tid = threadIdx.x;
    const int m0 = blockIdx.x * 128;   // gridDim.x = 1024
    const int n0 = blockIdx.y * 64;    // gridDim.y = 16
    const int tm = tid >> 4;
    const int tn = tid & 15;

    const int lr = tid >> 2;
    const int lc = (tid & 3) * 4;

    const float* Aptr  = A + (size_t)(m0 + lr) * 256 + lc;
    const float* Aptr2 = A + (size_t)(m0 + 64 + lr) * 256 + lc;
    const float* Wptr  = W + (size_t)(n0 + lr) * 256 + lc;

    float2 acc[8][2];
#pragma unroll
    for (int i = 0; i < 8; ++i) { acc[i][0] = make_float2(0.f, 0.f); acc[i][1] = make_float2(0.f, 0.f); }

    float4 la0 = *(const float4*)(Aptr);
    float4 la1 = *(const float4*)(Aptr2);
    float4 lb  = *(const float4*)(Wptr);
#pragma unroll
    for (int i = 0; i < 4; ++i) {
        As[0][lc + i][lr]      = (&la0.x)[i];
        As[0][lc + i][64 + lr] = (&la1.x)[i];
        Bs[0][lc + i][lr]      = (&lb.x)[i];
    }
    __syncthreads();

    for (int kt = 0; kt < 16; ++kt) {
        const int buf = kt & 1;
        if (kt < 15) {
            la0 = *(const float4*)(Aptr  + (kt + 1) * 16);
            la1 = *(const float4*)(Aptr2 + (kt + 1) * 16);
            lb  = *(const float4*)(Wptr  + (kt + 1) * 16);
        }
#pragma unroll
        for (int kk = 0; kk < GBK; ++kk) {
            float4 aF0 = *(const float4*)&As[buf][kk][tm * 8];
            float4 aF1 = *(const float4*)&As[buf][kk][tm * 8 + 4];
            float4 bF  = *(const float4*)&Bs[buf][kk][tn * 4];
            float2 bp0 = make_float2(bF.x, bF.y);
            float2 bp1 = make_float2(bF.z, bF.w);
            float av[8] = {aF0.x, aF0.y, aF0.z, aF0.w, aF1.x, aF1.y, aF1.z, aF1.w};
#pragma unroll
            for (int i = 0; i < 8; ++i) {
                float2 ap = make_float2(av[i], av[i]);
                acc[i][0] = fma2(acc[i][0], ap, bp0);
                acc[i][1] = fma2(acc[i][1], ap, bp1);
            }
        }
        if (kt < 15) {
            const int nb = buf ^ 1;
#pragma unroll
            for (int i = 0; i < 4; ++i) {
                As[nb][lc + i][lr]      = (&la0.x)[i];
                As[nb][lc + i][64 + lr] = (&la1.x)[i];
                Bs[nb][lc + i][lr]      = (&lb.x)[i];
            }
        }
        __syncthreads();
    }

    const int n = n0 + tn * 4;
    float4 bi4 = *(const float4*)(bih + n);
    float4 bh4 = *(const float4*)(bhh + n);
    float4 bias = make_float4(bi4.x + bh4.x, bi4.y + bh4.y, bi4.z + bh4.z, bi4.w + bh4.w);
    const int g      = n >> 8;
    const int col256 = n & 255;
    const int cg     = col256 >> 5;
    const int j0     = col256 & 31;
    const int bb     = m0 >> 10;
    const int t0     = (m0 & 1023) + tm * 8;
#pragma unroll
    for (int mi = 0; mi < 8; ++mi) {
        float4 o;
        o.x = acc[mi][0].x + bias.x;
        o.y = acc[mi][0].y + bias.y;
        o.z = acc[mi][1].x + bias.z;
        o.w = acc[mi][1].y + bias.w;
        *(float4*)(g_xp + ((((size_t)(t0 + mi) * 8 + cg) * 4 + g) * 128 + bb) * 32 + j0) = o;
    }
}

// =======================================================================
// Recurrence, flat grid + per-group flag barrier. 512 threads/CTA, 16 warps.
// Grid: 128 blocks = 16 groups(bgrp) x 8 CTAs(cgrp). Block: 8 batches x
// 32 cols (128 gate rows).
// Warp w owns rows [w*8, w*8+8). Lane: kq=lane&7 (32-k slice), rq=lane>>3;
// lane owns rows w*8+rq and w*8+4+rq (2 rows x 32 k = 64 weight floats in
// regs, compile-time indexed). LDS per warp per step: 8b x 8 = 64 (same
// 128B-unique/instr broadcast pattern as R8; per-SMSP LDS issue 512 cyc).
// 4 warps/SMSP hide the LDS/SHFL dependency chains that bounded R8.
// =======================================================================
__global__ void __launch_bounds__(TPBR, 1)
lstm_rec(const float* __restrict__ Whh, int layer) {
    float* HS = layer ? g_h2s : g_h1s;

    const int tid  = threadIdx.x;
    const int lane = tid & 31;
    const int warp = tid >> 5;          // 0..15
    const int cgrp = blockIdx.x & 7;
    const int bgrp = blockIdx.x >> 3;

    const int kq = lane & 7;            // k-slice: k = kq*32 .. +31
    const int rq = lane >> 3;           // 0..3

    // 2 rows x 16 float2 weights in registers (compile-time indexed)
    float2 Wr[2][16];
#pragma unroll
    for (int i = 0; i < 2; ++i) {
        const int r = warp * 8 + rq + i * 4;
        const int Wrow = (r >> 5) * VD + cgrp * 32 + (r & 31);
        const float4* ws = (const float4*)(Whh + (size_t)Wrow * VD + kq * 32);
#pragma unroll
        for (int c8 = 0; c8 < 8; ++c8) {
            float4 w4 = ws[c8];
            Wr[i][2 * c8]     = make_float2(w4.x, w4.y);
            Wr[i][2 * c8 + 1] = make_float2(w4.z, w4.w);
        }
    }

    // cell ownership: tid<256, b_loc=tid>>5, col=tid&31
    const bool cell_act = (tid < 256);
    const int b_loc  = tid >> 5;
    const int ccol   = tid & 31;
    const int b_glob = bgrp * 8 + (b_loc & 7);
    float cstate = 0.f;

    __shared__ float4 h_sm4[8 * 72];      // [8 b][8 kq-slices @ kq*9][8 f4]
    __shared__ float  gates_sm[8][128];

    const unsigned gen0 = *(volatile unsigned*)&g_flag[bgrp * 32 + cgrp];

    // prefetch x_proj for t=0
    float xg[4] = {0.f, 0.f, 0.f, 0.f};
    if (cell_act) {
#pragma unroll
        for (int g = 0; g < 4; ++g)
            xg[g] = __ldcs(g_xp + ((((size_t)0 * 8 + cgrp) * 4 + g) * 128 + b_glob) * 32 + ccol);
    }

    for (int t = 0; t < SEQT; ++t) {
        // ---- stage h(t-1): 512 float4, one per thread ----
        {
            const int b  = tid >> 6;
            const int c4 = tid & 63;
            const int dst = b * 72 + (c4 >> 3) * 9 + (c4 & 7);
            if (t == 0) {
                h_sm4[dst] = make_float4(0.f, 0.f, 0.f, 0.f);
            } else {
                const float4* src = (const float4*)(g_hbuf + (size_t)(t & 1) * (BATCH * VD)) + bgrp * 512;
                h_sm4[dst] = __ldcg(src + tid);
            }
        }
        __syncthreads();

        // ---- gates = h . Whh^T ----
#pragma unroll 2
        for (int b = 0; b < 8; ++b) {
            const float4* hrow = h_sm4 + b * 72 + kq * 9;
            float2 a0 = make_float2(0.f, 0.f);
            float2 a1 = make_float2(0.f, 0.f);
#pragma unroll
            for (int c8 = 0; c8 < 8; ++c8) {
                float4 hv = hrow[c8];
                float2 h01 = make_float2(hv.x, hv.y);
                float2 h23 = make_float2(hv.z, hv.w);
                a0 = fma2(a0, Wr[0][2 * c8],     h01);
                a0 = fma2(a0, Wr[0][2 * c8 + 1], h23);
                a1 = fma2(a1, Wr[1][2 * c8],     h01);
                a1 = fma2(a1, Wr[1][2 * c8 + 1], h23);
            }
            // reduce over 8 kq lanes (lane bits 0..2)
#pragma unroll
            for (int m = 1; m < 8; m <<= 1) {
                a0 = add2(a0, shfl_xor2(a0, m));
                a1 = add2(a1, shfl_xor2(a1, m));
            }
            if (kq == 0) {
                const int rb = warp * 8 + rq;
                gates_sm[b][rb]     = a0.x + a0.y;
                gates_sm[b][rb + 4] = a1.x + a1.y;
            }
        }
        __syncthreads();

        // ---- cell update: thread owns (batch=b_loc, col=ccol), tid<256 ----
        if (cell_act) {
            const float gi = gates_sm[b_loc][ccol]      + xg[0];
            const float gf = gates_sm[b_loc][32 + ccol] + xg[1];
            const float gc = gates_sm[b_loc][64 + ccol] + xg[2];
            const float go = gates_sm[b_loc][96 + ccol] + xg[3];
            const float i_ = sigmoidf_(gi);
            const float f_ = sigmoidf_(gf);
            const float z_ = tanhf(gc);
            const float o_ = sigmoidf_(go);
            cstate = f_ * cstate + i_ * z_;
            const float hv = o_ * tanhf(cstate);
            g_hbuf[(size_t)((t + 1) & 1) * (BATCH * VD) + b_glob * VD + cgrp * 32 + ccol] = hv;
            __stcs(HS + ((size_t)b_glob * SEQT + t) * VD + cgrp * 32 + ccol, hv);

            // prefetch x_proj for t+1 (hide under barrier)
            if (t + 1 < SEQT) {
#pragma unroll
                for (int g = 0; g < 4; ++g)
                    xg[g] = __ldcs(g_xp + ((((size_t)(t + 1) * 8 + cgrp) * 4 + g) * 128 + b_glob) * 32 + ccol);
            }
            __threadfence();   // order hv stores before this CTA's flag release
        }

        // ---- per-group flag barrier (spread-addr writes, lane-parallel poll) ----
        const unsigned target = gen0 + (unsigned)(t + 1);
        __syncthreads();
        if (warp == 0) {
            if (lane == 0) atomicExch(&g_flag[bgrp * 32 + cgrp], target);
            if (lane < 8) {
                const unsigned* f = &g_flag[bgrp * 32 + lane];
                while ((int)(ld_acq(f) - target) < 0) { }
            }
        }
        __syncthreads();
    }
}

// ---------------- fc weight row-normalization (1 warp per row) ----------------
__global__ void __launch_bounds__(32)
norm_fc(const float* __restrict__ w) {
    const int o = blockIdx.x;
    const int lane = threadIdx.x;
    float4 v0 = *(const float4*)(w + o * VD + lane * 8);
    float4 v1 = *(const float4*)(w + o * VD + lane * 8 + 4);
    float s = v0.x * v0.x + v0.y * v0.y + v0.z * v0.z + v0.w * v0.w
            + v1.x * v1.x + v1.y * v1.y + v1.z * v1.z + v1.w * v1.w;
#pragma unroll
    for (int m = 16; m > 0; m >>= 1) s += __shfl_xor_sync(0xffffffffu, s, m);
    const float inv = rsqrtf(s);
    float4 o0 = make_float4(v0.x * inv, v0.y * inv, v0.z * inv, v0.w * inv);
    float4 o1 = make_float4(v1.x * inv, v1.y * inv, v1.z * inv, v1.w * inv);
    *(float4*)(g_wn + o * VD + lane * 8)     = o0;
    *(float4*)(g_wn + o * VD + lane * 8 + 4) = o1;
}

// ---------------- final FC: out[M,256] = h2s[M,256] @ wn^T + b ----------------
__global__ void __launch_bounds__(256)
fc_kernel(const float* __restrict__ fc_b, float* __restrict__ out) {
    __shared__ float As[16][68];
    __shared__ float Bs[16][68];
    const int tid = threadIdx.x;
    const int bm = blockIdx.x * 64;
    const int bn = blockIdx.y * 64;
    const int tx = tid & 15;
    const int ty = tid >> 4;
    const int lr = tid >> 2;
    const int lc = (tid & 3) * 4;

    float acc[4][4];
#pragma unroll
    for (int i = 0; i < 4; ++i)
#pragma unroll
        for (int j = 0; j < 4; ++j) acc[i][j] = 0.f;

    for (int k0 = 0; k0 < VD; k0 += 16) {
        float4 a4 = *(const float4*)(g_h2s + ((size_t)(bm + lr)) * VD + k0 + lc);
        float4 b4 = *(const float4*)(g_wn + (bn + lr) * VD + k0 + lc);
        As[lc + 0][lr] = a4.x; As[lc + 1][lr] = a4.y;
        As[lc + 2][lr] = a4.z; As[lc + 3][lr] = a4.w;
        Bs[lc + 0][lr] = b4.x; Bs[lc + 1][lr] = b4.y;
        Bs[lc + 2][lr] = b4.z; Bs[lc + 3][lr] = b4.w;
        __syncthreads();
#pragma unroll
        for (int kk = 0; kk < 16; ++kk) {
            const float4 av = *(const float4*)&As[kk][ty * 4];
            const float4 bv = *(const float4*)&Bs[kk][tx * 4];
            acc[0][0] += av.x * bv.x; acc[0][1] += av.x * bv.y;
            acc[0][2] += av.x * bv.z; acc[0][3] += av.x * bv.w;
            acc[1][0] += av.y * bv.x; acc[1][1] += av.y * bv.y;
            acc[1][2] += av.y * bv.z; acc[1][3] += av.y * bv.w;
            acc[2][0] += av.z * bv.x; acc[2][1] += av.z * bv.y;
            acc[2][2] += av.z * bv.z; acc[2][3] += av.z * bv.w;
            acc[3][0] += av.w * bv.x; acc[3][1] += av.w * bv.y;
            acc[3][2] += av.w * bv.z; acc[3][3] += av.w * bv.w;
        }
        __syncthreads();
    }

#pragma unroll
    for (int i = 0; i < 4; ++i) {
        const size_t row = (size_t)(bm + ty * 4 + i) * VD + bn + tx * 4;
#pragma unroll
        for (int j = 0; j < 4; ++j)
            out[row + j] = acc[i][j] + fc_b[bn + tx * 4 + j];
    }
}

// ---------------- launch ----------------
extern "C" void kernel_launch(void* const* d_in, const int* in_sizes, int n_in,
                              void* d_out, int out_size) {
    (void)in_sizes; (void)n_in; (void)out_size;
    const float* x    = (const float*)d_in[0];
    const float* Wih1 = (const float*)d_in[1];
    const float* Whh1 = (const float*)d_in[2];
    const float* bih1 = (const float*)d_in[3];
    const float* bhh1 = (const float*)d_in[4];
    const float* Wih2 = (const float*)d_in[5];
    const float* Whh2 = (const float*)d_in[6];
    const float* bih2 = (const float*)d_in[7];
    const float* bhh2 = (const float*)d_in[8];
    const float* fcw  = (const float*)d_in[9];
    const float* fcb  = (const float*)d_in[10];
    float* out = (float*)d_out;

    float* h1s_ptr = nullptr;
    cudaGetSymbolAddress((void**)&h1s_ptr, g_h1s);

    norm_fc<<<256, 32>>>(fcw);
    dim3 ggrid(1024, 16);
    gemm_xproj<<<ggrid, 256>>>(x, Wih1, bih1, bhh1);
    lstm_rec<<<128, TPBR>>>(Whh1, 0);
    gemm_xproj<<<ggrid, 256>>>(h1s_ptr, Wih2, bih2, bhh2);
    lstm_rec<<<128, TPBR>>>(Whh2, 1);
    dim3 fgrid(BATCH * SEQT / 64, VD / 64);
    fc_kernel<<<fgrid, 256>>>(fcb, out);
}

// round 10
// speedup vs baseline: 1.2009x; 1.2009x over previous
#include <cuda_runtime.h>
#include <cstdint>
#include <cstddef>

#define BATCH 128
#define SEQT  1024
#define VD    256
#define TPB   256

// ---------------- device scratch (static, no allocation) ----------------
__device__ float g_xp[134217728];                       // x_proj permuted [T][cg8][g4][b128][col32]
__device__ float g_h1s[BATCH * SEQT * VD];              // layer-1 hidden states [B,T,V]
__device__ float g_h2s[BATCH * SEQT * VD];              // layer-2 hidden states [B,T,V]
__device__ __align__(128) float g_hbuf[2 * BATCH * VD]; // double-buffered h exchange
__device__ float g_wn[VD * VD];                         // row-normalized fc weight
// per-group flag barrier: 16 groups x 8 CTA flags (first 32B of a 128B line)
__device__ __align__(128) unsigned g_flag[16 * 32];

// ---------------- packed f32x2 helpers ----------------
__device__ __forceinline__ float2 fma2(float2 acc, float2 w, float2 v) {
    unsigned long long ua, uw, uv;
    ua = *reinterpret_cast<unsigned long long*>(&acc);
    uw = *reinterpret_cast<unsigned long long*>(&w);
    uv = *reinterpret_cast<unsigned long long*>(&v);
    asm("fma.rn.f32x2 %0, %1, %2, %0;" : "+l"(ua) : "l"(uw), "l"(uv));
    return *reinterpret_cast<float2*>(&ua);
}

__device__ __forceinline__ float2 add2(float2 a, float2 b) {
    unsigned long long ua, ub;
    ua = *reinterpret_cast<unsigned long long*>(&a);
    ub = *reinterpret_cast<unsigned long long*>(&b);
    asm("add.rn.f32x2 %0, %0, %1;" : "+l"(ua) : "l"(ub));
    return *reinterpret_cast<float2*>(&ua);
}

__device__ __forceinline__ float2 shfl_xor2(float2 v, int m) {
    unsigned long long u = *reinterpret_cast<unsigned long long*>(&v);
    u = __shfl_xor_sync(0xffffffffu, u, m);
    return *reinterpret_cast<float2*>(&u);
}

__device__ __forceinline__ float sigmoidf_(float x) {
    return 1.0f / (1.0f + __expf(-x));
}

__device__ __forceinline__ unsigned ld_acq(const unsigned* p) {
    unsigned v;
    asm volatile("ld.acquire.gpu.global.u32 %0, [%1];" : "=r"(v) : "l"(p) : "memory");
    return v;
}

__device__ __forceinline__ void exch_release(unsigned* p, unsigned v) {
    unsigned d;
    asm volatile("atom.release.gpu.global.exch.b32 %0, [%1], %2;"
                 : "=r"(d) : "l"(p), "r"(v) : "memory");
}

// =======================================================================
// GEMM: x_proj[m][n] = A[m][0:256] . W[n][0:256] + bih[n] + bhh[n]
// Output PERMUTED into g_xp: [t][cg(8)][g(4)][b(128)][col(32)]
// =======================================================================
#define GBK 16

__global__ void __launch_bounds__(256)
gemm_xproj(const float* __restrict__ A, const float* __restrict__ W,
           const float* __restrict__ bih, const float* __restrict__ bhh) {
    __shared__ float As[2][GBK][132];
    __shared__ float Bs[2][GBK][68];

    const int tid = threadIdx.x;
    const int m0 = blockIdx.x * 128;   // gridDim.x = 1024
    const int n0 = blockIdx.y * 64;    // gridDim.y = 16
    const int tm = tid >> 4;
    const int tn = tid & 15;

    const int lr = tid >> 2;
    const int lc = (tid & 3) * 4;

    const float* Aptr  = A + (size_t)(m0 + lr) * 256 + lc;
    const float* Aptr2 = A + (size_t)(m0 + 64 + lr) * 256 + lc;
    const float* Wptr  = W + (size_t)(n0 + lr) * 256 + lc;

    float2 acc[8][2];
#pragma unroll
    for (int i = 0; i < 8; ++i) { acc[i][0] = make_float2(0.f, 0.f); acc[i][1] = make_float2(0.f, 0.f); }

    float4 la0 = *(const float4*)(Aptr);
    float4 la1 = *(const float4*)(Aptr2);
    float4 lb  = *(const float4*)(Wptr);
#pragma unroll
    for (int i = 0; i < 4; ++i) {
        As[0][lc + i][lr]      = (&la0.x)[i];
        As[0][lc + i][64 + lr] = (&la1.x)[i];
        Bs[0][lc + i][lr]      = (&lb.x)[i];
    }
    __syncthreads();

    for (int kt = 0; kt < 16; ++kt) {
        const int buf = kt & 1;
        if (kt < 15) {
            la0 = *(const float4*)(Aptr  + (kt + 1) * 16);
            la1 = *(const float4*)(Aptr2 + (kt + 1) * 16);
            lb  = *(const float4*)(Wptr  + (kt + 1) * 16);
        }
#pragma unroll
        for (int kk = 0; kk < GBK; ++kk) {
            float4 aF0 = *(const float4*)&As[buf][kk][tm * 8];
            float4 aF1 = *(const float4*)&As[buf][kk][tm * 8 + 4];
            float4 bF  = *(const float4*)&Bs[buf][kk][tn * 4];
            float2 bp0 = make_float2(bF.x, bF.y);
            float2 bp1 = make_float2(bF.z, bF.w);
            float av[8] = {aF0.x, aF0.y, aF0.z, aF0.w, aF1.x, aF1.y, aF1.z, aF1.w};
#pragma unroll
            for (int i = 0; i < 8; ++i) {
                float2 ap = make_float2(av[i], av[i]);
                acc[i][0] = fma2(acc[i][0], ap, bp0);
                acc[i][1] = fma2(acc[i][1], ap, bp1);
            }
        }
        if (kt < 15) {
            const int nb = buf ^ 1;
#pragma unroll
            for (int i = 0; i < 4; ++i) {
                As[nb][lc + i][lr]      = (&la0.x)[i];
                As[nb][lc + i][64 + lr] = (&la1.x)[i];
                Bs[nb][lc + i][lr]      = (&lb.x)[i];
            }
        }
        __syncthreads();
    }

    const int n = n0 + tn * 4;
    float4 bi4 = *(const float4*)(bih + n);
    float4 bh4 = *(const float4*)(bhh + n);
    float4 bias = make_float4(bi4.x + bh4.x, bi4.y + bh4.y, bi4.z + bh4.z, bi4.w + bh4.w);
    const int g      = n >> 8;
    const int col256 = n & 255;
    const int cg     = col256 >> 5;
    const int j0     = col256 & 31;
    const int bb     = m0 >> 10;
    const int t0     = (m0 & 1023) + tm * 8;
#pragma unroll
    for (int mi = 0; mi < 8; ++mi) {
        float4 o;
        o.x = acc[mi][0].x + bias.x;
        o.y = acc[mi][0].y + bias.y;
        o.z = acc[mi][1].x + bias.z;
        o.w = acc[mi][1].y + bias.w;
        *(float4*)(g_xp + ((((size_t)(t0 + mi) * 8 + cg) * 4 + g) * 128 + bb) * 32 + j0) = o;
    }
}

// =======================================================================
// Recurrence, flat grid + per-group flag barrier. 256 threads/CTA.
// Grid: 128 blocks = 16 groups(bgrp) x 8 CTAs(cgrp). Block: 8 batches x
// 32 cols (128 gate rows). Warp w: rows [w*16, w*16+16).
// Lane: kq=lane&7 (32-k slice), rq=lane>>3; lane owns rows w*16+rq+4i
// (i=0..3): 4 rows x 32 k = 128 weight floats in regs (compile-time idx).
// Gates loop processes 2 batches/iteration -> 8 independent fma2 chains.
// Barrier: release-exch by tid0, every warp polls all 8 flags (acquire).
// =======================================================================
__global__ void __launch_bounds__(TPB, 1)
lstm_rec(const float* __restrict__ Whh, int layer) {
    float* HS = layer ? g_h2s : g_h1s;

    const int tid  = threadIdx.x;
    const int lane = tid & 31;
    const int warp = tid >> 5;
    const int cgrp = blockIdx.x & 7;
    const int bgrp = blockIdx.x >> 3;

    const int kq = lane & 7;     // k-slice: k = kq*32 .. +31
    const int rq = lane >> 3;    // 0..3

    // 4 rows x 16 float2 weights in registers (compile-time indexed)
    float2 Wr[4][16];
#pragma unroll
    for (int i = 0; i < 4; ++i) {
        const int r = warp * 16 + rq + i * 4;
        const int Wrow = (r >> 5) * VD + cgrp * 32 + (r & 31);
        const float4* ws = (const float4*)(Whh + (size_t)Wrow * VD + kq * 32);
#pragma unroll
        for (int c8 = 0; c8 < 8; ++c8) {
            float4 w4 = ws[c8];
            Wr[i][2 * c8]     = make_float2(w4.x, w4.y);
            Wr[i][2 * c8 + 1] = make_float2(w4.z, w4.w);
        }
    }

    // cell ownership: b_loc=tid>>5 (=warp), col=tid&31
    const int b_loc  = tid >> 5;
    const int ccol   = tid & 31;
    const int b_glob = bgrp * 8 + b_loc;
    float cstate = 0.f;

    __shared__ float4 h_sm4[8 * 72];      // [8 b][8 kq-slices @ kq*9][8 f4]
    __shared__ float  gates_sm[8][128];

    // flag barrier base state (all CTAs in group agree at launch)
    const unsigned gen0 = *(volatile unsigned*)&g_flag[bgrp * 32 + cgrp];

    // prefetch x_proj for t=0
    float xg[4];
#pragma unroll
    for (int g = 0; g < 4; ++g)
        xg[g] = __ldcs(g_xp + ((((size_t)0 * 8 + cgrp) * 4 + g) * 128 + b_glob) * 32 + ccol);

    for (int t = 0; t < SEQT; ++t) {
        // ---- stage h(t-1): 512 float4, 2 per thread ----
        if (t == 0) {
            float4 z = make_float4(0.f, 0.f, 0.f, 0.f);
#pragma unroll
            for (int i = 0; i < 2; ++i) {
                const int flat = tid + i * 256;
                const int b  = flat >> 6;
                const int c4 = flat & 63;
                h_sm4[b * 72 + (c4 >> 3) * 9 + (c4 & 7)] = z;
            }
        } else {
            const float4* src = (const float4*)(g_hbuf + (size_t)(t & 1) * (BATCH * VD)) + bgrp * 512;
#pragma unroll
            for (int i = 0; i < 2; ++i) {
                const int flat = tid + i * 256;
                const int b  = flat >> 6;
                const int c4 = flat & 63;
                h_sm4[b * 72 + (c4 >> 3) * 9 + (c4 & 7)] = __ldcg(src + flat);
            }
        }
        __syncthreads();

        // ---- gates = h . Whh^T (2 batches per iteration, 8 acc chains) ----
#pragma unroll
        for (int bp = 0; bp < 8; bp += 2) {
            const float4* hrowA = h_sm4 + bp * 72 + kq * 9;
            const float4* hrowB = hrowA + 72;
            float2 a0 = make_float2(0.f, 0.f), a1 = make_float2(0.f, 0.f);
            float2 a2 = make_float2(0.f, 0.f), a3 = make_float2(0.f, 0.f);
            float2 b0 = make_float2(0.f, 0.f), b1 = make_float2(0.f, 0.f);
            float2 b2 = make_float2(0.f, 0.f), b3 = make_float2(0.f, 0.f);
#pragma unroll
            for (int c8 = 0; c8 < 8; ++c8) {
                float4 hvA = hrowA[c8];
                float4 hvB = hrowB[c8];
                float2 hA01 = make_float2(hvA.x, hvA.y);
                float2 hA23 = make_float2(hvA.z, hvA.w);
                float2 hB01 = make_float2(hvB.x, hvB.y);
                float2 hB23 = make_float2(hvB.z, hvB.w);
                a0 = fma2(a0, Wr[0][2 * c8],     hA01);
                a0 = fma2(a0, Wr[0][2 * c8 + 1], hA23);
                a1 = fma2(a1, Wr[1][2 * c8],     hA01);
                a1 = fma2(a1, Wr[1][2 * c8 + 1], hA23);
                a2 = fma2(a2, Wr[2][2 * c8],     hA01);
                a2 = fma2(a2, Wr[2][2 * c8 + 1], hA23);
                a3 = fma2(a3, Wr[3][2 * c8],     hA01);
                a3 = fma2(a3, Wr[3][2 * c8 + 1], hA23);
                b0 = fma2(b0, Wr[0][2 * c8],     hB01);
                b0 = fma2(b0, Wr[0][2 * c8 + 1], hB23);
                b1 = fma2(b1, Wr[1][2 * c8],     hB01);
                b1 = fma2(b1, Wr[1][2 * c8 + 1], hB23);
                b2 = fma2(b2, Wr[2][2 * c8],     hB01);
                b2 = fma2(b2, Wr[2][2 * c8 + 1], hB23);
                b3 = fma2(b3, Wr[3][2 * c8],     hB01);
                b3 = fma2(b3, Wr[3][2 * c8 + 1], hB23);
            }
            // reduce over 8 kq lanes (lane bits 0..2)
#pragma unroll
            for (int m = 1; m < 8; m <<= 1) {
                a0 = add2(a0, shfl_xor2(a0, m));
                a1 = add2(a1, shfl_xor2(a1, m));
                a2 = add2(a2, shfl_xor2(a2, m));
                a3 = add2(a3, shfl_xor2(a3, m));
                b0 = add2(b0, shfl_xor2(b0, m));
                b1 = add2(b1, shfl_xor2(b1, m));
                b2 = add2(b2, shfl_xor2(b2, m));
                b3 = add2(b3, shfl_xor2(b3, m));
            }
            if (kq == 0) {
                const int rb = warp * 16 + rq;
                gates_sm[bp][rb]          = a0.x + a0.y;
                gates_sm[bp][rb + 4]      = a1.x + a1.y;
                gates_sm[bp][rb + 8]      = a2.x + a2.y;
                gates_sm[bp][rb + 12]     = a3.x + a3.y;
                gates_sm[bp + 1][rb]      = b0.x + b0.y;
                gates_sm[bp + 1][rb + 4]  = b1.x + b1.y;
                gates_sm[bp + 1][rb + 8]  = b2.x + b2.y;
                gates_sm[bp + 1][rb + 12] = b3.x + b3.y;
            }
        }
        __syncthreads();

        // ---- cell update: thread owns (batch=b_loc, col=ccol) ----
        {
            const float gi = gates_sm[b_loc][ccol]      + xg[0];
            const float gf = gates_sm[b_loc][32 + ccol] + xg[1];
            const float gc = gates_sm[b_loc][64 + ccol] + xg[2];
            const float go = gates_sm[b_loc][96 + ccol] + xg[3];
            const float i_ = sigmoidf_(gi);
            const float f_ = sigmoidf_(gf);
            const float z_ = tanhf(gc);
            const float o_ = sigmoidf_(go);
            cstate = f_ * cstate + i_ * z_;
            const float hv = o_ * tanhf(cstate);
            g_hbuf[(size_t)((t + 1) & 1) * (BATCH * VD) + b_glob * VD + cgrp * 32 + ccol] = hv;
            __stcs(HS + ((size_t)b_glob * SEQT + t) * VD + cgrp * 32 + ccol, hv);

            // prefetch x_proj for t+1 (hide under barrier)
            if (t + 1 < SEQT) {
#pragma unroll
                for (int g = 0; g < 4; ++g)
                    xg[g] = __ldcs(g_xp + ((((size_t)(t + 1) * 8 + cgrp) * 4 + g) * 128 + b_glob) * 32 + ccol);
            }
        }

        // ---- per-group flag barrier ----
        // sync orders all threads' g_hbuf stores before tid0's release-exch;
        // every warp then polls all 8 flags with acquire loads and proceeds
        // independently (no release __syncthreads on the critical path).
        const unsigned target = gen0 + (unsigned)(t + 1);
        __syncthreads();
        if (tid == 0) exch_release(&g_flag[bgrp * 32 + cgrp], target);
        if (lane < 8) {
            const unsigned* f = &g_flag[bgrp * 32 + lane];
            while ((int)(ld_acq(f) - target) < 0) { }
        }
        __syncwarp();
    }
}

// ---------------- fc weight row-normalization (1 warp per row) ----------------
__global__ void __launch_bounds__(32)
norm_fc(const float* __restrict__ w) {
    const int o = blockIdx.x;
    const int lane = threadIdx.x;
    float4 v0 = *(const float4*)(w + o * VD + lane * 8);
    float4 v1 = *(const float4*)(w + o * VD + lane * 8 + 4);
    float s = v0.x * v0.x + v0.y * v0.y + v0.z * v0.z + v0.w * v0.w
            + v1.x * v1.x + v1.y * v1.y + v1.z * v1.z + v1.w * v1.w;
#pragma unroll
    for (int m = 16; m > 0; m >>= 1) s += __shfl_xor_sync(0xffffffffu, s, m);
    const float inv = rsqrtf(s);
    float4 o0 = make_float4(v0.x * inv, v0.y * inv, v0.z * inv, v0.w * inv);
    float4 o1 = make_float4(v1.x * inv, v1.y * inv, v1.z * inv, v1.w * inv);
    *(float4*)(g_wn + o * VD + lane * 8)     = o0;
    *(float4*)(g_wn + o * VD + lane * 8 + 4) = o1;
}

// ---------------- final FC: out[M,256] = h2s[M,256] @ wn^T + b ----------------
__global__ void __launch_bounds__(256)
fc_kernel(const float* __restrict__ fc_b, float* __restrict__ out) {
    __shared__ float As[16][68];
    __shared__ float Bs[16][68];
    const int tid = threadIdx.x;
    const int bm = blockIdx.x * 64;
    const int bn = blockIdx.y * 64;
    const int tx = tid & 15;
    const int ty = tid >> 4;
    const int lr = tid >> 2;
    const int lc = (tid & 3) * 4;

    float acc[4][4];
#pragma unroll
    for (int i = 0; i < 4; ++i)
#pragma unroll
        for (int j = 0; j < 4; ++j) acc[i][j] = 0.f;

    for (int k0 = 0; k0 < VD; k0 += 16) {
        float4 a4 = *(const float4*)(g_h2s + ((size_t)(bm + lr)) * VD + k0 + lc);
        float4 b4 = *(const float4*)(g_wn + (bn + lr) * VD + k0 + lc);
        As[lc + 0][lr] = a4.x; As[lc + 1][lr] = a4.y;
        As[lc + 2][lr] = a4.z; As[lc + 3][lr] = a4.w;
        Bs[lc + 0][lr] = b4.x; Bs[lc + 1][lr] = b4.y;
        Bs[lc + 2][lr] = b4.z; Bs[lc + 3][lr] = b4.w;
        __syncthreads();
#pragma unroll
        for (int kk = 0; kk < 16; ++kk) {
            const float4 av = *(const float4*)&As[kk][ty * 4];
            const float4 bv = *(const float4*)&Bs[kk][tx * 4];
            acc[0][0] += av.x * bv.x; acc[0][1] += av.x * bv.y;
            acc[0][2] += av.x * bv.z; acc[0][3] += av.x * bv.w;
            acc[1][0] += av.y * bv.x; acc[1][1] += av.y * bv.y;
            acc[1][2] += av.y * bv.z; acc[1][3] += av.y * bv.w;
            acc[2][0] += av.z * bv.x; acc[2][1] += av.z * bv.y;
            acc[2][2] += av.z * bv.z; acc[2][3] += av.z * bv.w;
            acc[3][0] += av.w * bv.x; acc[3][1] += av.w * bv.y;
            acc[3][2] += av.w * bv.z; acc[3][3] += av.w * bv.w;
        }
        __syncthreads();
    }

#pragma unroll
    for (int i = 0; i < 4; ++i) {
        const size_t row = (size_t)(bm + ty * 4 + i) * VD + bn + tx * 4;
#pragma unroll
        for (int j = 0; j < 4; ++j)
            out[row + j] = acc[i][j] + fc_b[bn + tx * 4 + j];
    }
}

// ---------------- launch ----------------
extern "C" void kernel_launch(void* const* d_in, const int* in_sizes, int n_in,
                              void* d_out, int out_size) {
    (void)in_sizes; (void)n_in; (void)out_size;
    const float* x    = (const float*)d_in[0];
    const float* Wih1 = (const float*)d_in[1];
    const float* Whh1 = (const float*)d_in[2];
    const float* bih1 = (const float*)d_in[3];
    const float* bhh1 = (const float*)d_in[4];
    const float* Wih2 = (const float*)d_in[5];
    const float* Whh2 = (const float*)d_in[6];
    const float* bih2 = (const float*)d_in[7];
    const float* bhh2 = (const float*)d_in[8];
    const float* fcw  = (const float*)d_in[9];
    const float* fcb  = (const float*)d_in[10];
    float* out = (float*)d_out;

    float* h1s_ptr = nullptr;
    cudaGetSymbolAddress((void**)&h1s_ptr, g_h1s);

    norm_fc<<<256, 32>>>(fcw);
    dim3 ggrid(1024, 16);
    gemm_xproj<<<ggrid, 256>>>(x, Wih1, bih1, bhh1);
    lstm_rec<<<128, TPB>>>(Whh1, 0);
    gemm_xproj<<<ggrid, 256>>>(h1s_ptr, Wih2, bih2, bhh2);
    lstm_rec<<<128, TPB>>>(Whh2, 1);
    dim3 fgrid(BATCH * SEQT / 64, VD / 64);
    fc_kernel<<<fgrid, 256>>>(fcb, out);
}

// round 12
// speedup vs baseline: 1.8575x; 1.5468x over previous
#include <cuda_runtime.h>
#include <cstdint>
#include <cstddef>

#define BATCH 128
#define SEQT  1024
#define VD    256
#define TPB   256

// ---------------- device scratch (static, no allocation) ----------------
__device__ float g_xp[134217728];                       // x_proj permuted [T][cg8][g4][b128][col32]
__device__ float g_h1s[BATCH * SEQT * VD];              // layer-1 hidden states [B,T,V]
__device__ float g_h2s[BATCH * SEQT * VD];              // layer-2 hidden states [B,T,V]
__device__ __align__(128) float g_hbuf[2 * BATCH * VD]; // double-buffered h exchange
__device__ float g_wn[VD * VD];                         // row-normalized fc weight
// per-group flag barrier: 16 groups x 8 CTA flags (first 32B of a 128B line)
__device__ __align__(128) unsigned g_flag[16 * 32];

// ---------------- packed f32x2 helpers ----------------
__device__ __forceinline__ float2 fma2(float2 acc, float2 w, float2 v) {
    unsigned long long ua, uw, uv;
    ua = *reinterpret_cast<unsigned long long*>(&acc);
    uw = *reinterpret_cast<unsigned long long*>(&w);
    uv = *reinterpret_cast<unsigned long long*>(&v);
    asm("fma.rn.f32x2 %0, %1, %2, %0;" : "+l"(ua) : "l"(uw), "l"(uv));
    return *reinterpret_cast<float2*>(&ua);
}

__device__ __forceinline__ float2 add2(float2 a, float2 b) {
    unsigned long long ua, ub;
    ua = *reinterpret_cast<unsigned long long*>(&a);
    ub = *reinterpret_cast<unsigned long long*>(&b);
    asm("add.rn.f32x2 %0, %0, %1;" : "+l"(ua) : "l"(ub));
    return *reinterpret_cast<float2*>(&ua);
}

__device__ __forceinline__ float2 shfl_xor2(float2 v, int m) {
    unsigned long long u = *reinterpret_cast<unsigned long long*>(&v);
    u = __shfl_xor_sync(0xffffffffu, u, m);
    return *reinterpret_cast<float2*>(&u);
}

__device__ __forceinline__ float sigmoidf_(float x) {
    return 1.0f / (1.0f + __expf(-x));
}

__device__ __forceinline__ unsigned ld_acq(const unsigned* p) {
    unsigned v;
    asm volatile("ld.acquire.gpu.global.u32 %0, [%1];" : "=r"(v) : "l"(p) : "memory");
    return v;
}

__device__ __forceinline__ void exch_release(unsigned* p, unsigned v) {
    unsigned d;
    asm volatile("atom.release.gpu.global.exch.b32 %0, [%1], %2;"
                 : "=r"(d) : "l"(p), "r"(v) : "memory");
}

// =======================================================================
// GEMM: x_proj[m][n] = A[m][0:256] . W[n][0:256] + bih[n] + bhh[n]
// A: [131072][256] row-major. W: [1024][256] row-major.
// Output PERMUTED into g_xp: [t][cg(8)][g(4)][b(128)][col(32)]
// Tile: BM=128, BN=128, BK=8, 256 thr, TM=8, TN=8 (f32x2 inner product).
// B smem uses a CUMULATIVE stagger: element n stored at n + 4*(n>>5)
// (groups at [0,31],[36,67],[72,103],[108,139] -- disjoint, row width 144).
// Read at tx*8 + 4*(tx>>2): same mapping, float4-aligned, 2-way banks.
// =======================================================================
#define GBK 8

__global__ void __launch_bounds__(256)
gemm_xproj(const float* __restrict__ A, const float* __restrict__ W,
           const float* __restrict__ bih, const float* __restrict__ bhh) {
    __shared__ float As[2][GBK][132];
    __shared__ float Bs[2][GBK][144];

    const int tid = threadIdx.x;
    const int m0 = blockIdx.x * 128;   // gridDim.x = 1024
    const int n0 = blockIdx.y * 128;   // gridDim.y = 8
    const int tx = tid & 15;           // n subtile (8 cols)
    const int ty = tid >> 4;           // m subtile (8 rows)

    const int lr = tid >> 1;           // 0..127 (tile row for loads)
    const int lc = (tid & 1) * 4;      // k offset 0 or 4
    const int bsh = 4 * (lr >> 5);     // cumulative B stagger at store (n = lr)
    const int rsh = 4 * (tx >> 2);     // cumulative B stagger at read (n = tx*8)

    const float* Aptr = A + (size_t)(m0 + lr) * 256 + lc;
    const float* Wptr = W + (size_t)(n0 + lr) * 256 + lc;

    float2 acc[8][4];
#pragma unroll
    for (int i = 0; i < 8; ++i)
#pragma unroll
        for (int j = 0; j < 4; ++j) acc[i][j] = make_float2(0.f, 0.f);

    float4 la = *(const float4*)(Aptr);
    float4 lb = *(const float4*)(Wptr);
#pragma unroll
    for (int i = 0; i < 4; ++i) {
        As[0][lc + i][lr]       = (&la.x)[i];
        Bs[0][lc + i][lr + bsh] = (&lb.x)[i];
    }
    __syncthreads();

    for (int kt = 0; kt < 32; ++kt) {
        const int buf = kt & 1;
        if (kt < 31) {
            la = *(const float4*)(Aptr + (kt + 1) * 8);
            lb = *(const float4*)(Wptr + (kt + 1) * 8);
        }
#pragma unroll
        for (int kk = 0; kk < GBK; ++kk) {
            float4 a0 = *(const float4*)&As[buf][kk][ty * 8];
            float4 a1 = *(const float4*)&As[buf][kk][ty * 8 + 4];
            float4 b0 = *(const float4*)&Bs[buf][kk][tx * 8 + rsh];
            float4 b1 = *(const float4*)&Bs[buf][kk][tx * 8 + 4 + rsh];
            float2 bp[4];
            bp[0] = make_float2(b0.x, b0.y);
            bp[1] = make_float2(b0.z, b0.w);
            bp[2] = make_float2(b1.x, b1.y);
            bp[3] = make_float2(b1.z, b1.w);
            float av[8] = {a0.x, a0.y, a0.z, a0.w, a1.x, a1.y, a1.z, a1.w};
#pragma unroll
            for (int mi = 0; mi < 8; ++mi) {
                float2 ap = make_float2(av[mi], av[mi]);
                acc[mi][0] = fma2(acc[mi][0], ap, bp[0]);
                acc[mi][1] = fma2(acc[mi][1], ap, bp[1]);
                acc[mi][2] = fma2(acc[mi][2], ap, bp[2]);
                acc[mi][3] = fma2(acc[mi][3], ap, bp[3]);
            }
        }
        if (kt < 31) {
            const int nb = buf ^ 1;
#pragma unroll
            for (int i = 0; i < 4; ++i) {
                As[nb][lc + i][lr]       = (&la.x)[i];
                Bs[nb][lc + i][lr + bsh] = (&lb.x)[i];
            }
        }
        __syncthreads();
    }

    // epilogue: bias + permuted store (2x STG.128 per mi)
    const int n = n0 + tx * 8;
    float4 bi0 = *(const float4*)(bih + n);
    float4 bh0 = *(const float4*)(bhh + n);
    float4 bi1 = *(const float4*)(bih + n + 4);
    float4 bh1 = *(const float4*)(bhh + n + 4);
    float4 ba = make_float4(bi0.x + bh0.x, bi0.y + bh0.y, bi0.z + bh0.z, bi0.w + bh0.w);
    float4 bb4 = make_float4(bi1.x + bh1.x, bi1.y + bh1.y, bi1.z + bh1.z, bi1.w + bh1.w);

    const int g      = n >> 8;
    const int col256 = n & 255;
    const int cg     = col256 >> 5;
    const int j0     = col256 & 31;     // in {0,8,16,24}
    const int bb     = m0 >> 10;
    const int t0     = (m0 & 1023) + ty * 8;
#pragma unroll
    for (int mi = 0; mi < 8; ++mi) {
        float4 o0, o1;
        o0.x = acc[mi][0].x + ba.x;
        o0.y = acc[mi][0].y + ba.y;
        o0.z = acc[mi][1].x + ba.z;
        o0.w = acc[mi][1].y + ba.w;
        o1.x = acc[mi][2].x + bb4.x;
        o1.y = acc[mi][2].y + bb4.y;
        o1.z = acc[mi][3].x + bb4.z;
        o1.w = acc[mi][3].y + bb4.w;
        float* dst = g_xp + ((((size_t)(t0 + mi) * 8 + cg) * 4 + g) * 128 + bb) * 32 + j0;
        *(float4*)(dst)     = o0;
        *(float4*)(dst + 4) = o1;
    }
}

// =======================================================================
// Recurrence, flat grid + per-group flag barrier. 256 threads/CTA.
// (unchanged from R10: 4 rows/lane, 8-way k-split, 2-batch ILP,
//  release-exch + all-warps acquire-poll barrier)
// =======================================================================
__global__ void __launch_bounds__(TPB, 1)
lstm_rec(const float* __restrict__ Whh, int layer) {
    float* HS = layer ? g_h2s : g_h1s;

    const int tid  = threadIdx.x;
    const int lane = tid & 31;
    const int warp = tid >> 5;
    const int cgrp = blockIdx.x & 7;
    const int bgrp = blockIdx.x >> 3;

    const int kq = lane & 7;     // k-slice: k = kq*32 .. +31
    const int rq = lane >> 3;    // 0..3

    // 4 rows x 16 float2 weights in registers (compile-time indexed)
    float2 Wr[4][16];
#pragma unroll
    for (int i = 0; i < 4; ++i) {
        const int r = warp * 16 + rq + i * 4;
        const int Wrow = (r >> 5) * VD + cgrp * 32 + (r & 31);
        const float4* ws = (const float4*)(Whh + (size_t)Wrow * VD + kq * 32);
#pragma unroll
        for (int c8 = 0; c8 < 8; ++c8) {
            float4 w4 = ws[c8];
            Wr[i][2 * c8]     = make_float2(w4.x, w4.y);
            Wr[i][2 * c8 + 1] = make_float2(w4.z, w4.w);
        }
    }

    // cell ownership: b_loc=tid>>5 (=warp), col=tid&31
    const int b_loc  = tid >> 5;
    const int ccol   = tid & 31;
    const int b_glob = bgrp * 8 + b_loc;
    float cstate = 0.f;

    __shared__ float4 h_sm4[8 * 72];      // [8 b][8 kq-slices @ kq*9][8 f4]
    __shared__ float  gates_sm[8][128];

    const unsigned gen0 = *(volatile unsigned*)&g_flag[bgrp * 32 + cgrp];

    // prefetch x_proj for t=0
    float xg[4];
#pragma unroll
    for (int g = 0; g < 4; ++g)
        xg[g] = __ldcs(g_xp + ((((size_t)0 * 8 + cgrp) * 4 + g) * 128 + b_glob) * 32 + ccol);

    for (int t = 0; t < SEQT; ++t) {
        // ---- stage h(t-1): 512 float4, 2 per thread ----
        if (t == 0) {
            float4 z = make_float4(0.f, 0.f, 0.f, 0.f);
#pragma unroll
            for (int i = 0; i < 2; ++i) {
                const int flat = tid + i * 256;
                const int b  = flat >> 6;
                const int c4 = flat & 63;
                h_sm4[b * 72 + (c4 >> 3) * 9 + (c4 & 7)] = z;
            }
        } else {
            const float4* src = (const float4*)(g_hbuf + (size_t)(t & 1) * (BATCH * VD)) + bgrp * 512;
#pragma unroll
            for (int i = 0; i < 2; ++i) {
                const int flat = tid + i * 256;
                const int b  = flat >> 6;
                const int c4 = flat & 63;
                h_sm4[b * 72 + (c4 >> 3) * 9 + (c4 & 7)] = __ldcg(src + flat);
            }
        }
        __syncthreads();

        // ---- gates = h . Whh^T (2 batches per iteration, 8 acc chains) ----
#pragma unroll
        for (int bp = 0; bp < 8; bp += 2) {
            const float4* hrowA = h_sm4 + bp * 72 + kq * 9;
            const float4* hrowB = hrowA + 72;
            float2 a0 = make_float2(0.f, 0.f), a1 = make_float2(0.f, 0.f);
            float2 a2 = make_float2(0.f, 0.f), a3 = make_float2(0.f, 0.f);
            float2 b0 = make_float2(0.f, 0.f), b1 = make_float2(0.f, 0.f);
            float2 b2 = make_float2(0.f, 0.f), b3 = make_float2(0.f, 0.f);
#pragma unroll
            for (int c8 = 0; c8 < 8; ++c8) {
                float4 hvA = hrowA[c8];
                float4 hvB = hrowB[c8];
                float2 hA01 = make_float2(hvA.x, hvA.y);
                float2 hA23 = make_float2(hvA.z, hvA.w);
                float2 hB01 = make_float2(hvB.x, hvB.y);
                float2 hB23 = make_float2(hvB.z, hvB.w);
                a0 = fma2(a0, Wr[0][2 * c8],     hA01);
                a0 = fma2(a0, Wr[0][2 * c8 + 1], hA23);
                a1 = fma2(a1, Wr[1][2 * c8],     hA01);
                a1 = fma2(a1, Wr[1][2 * c8 + 1], hA23);
                a2 = fma2(a2, Wr[2][2 * c8],     hA01);
                a2 = fma2(a2, Wr[2][2 * c8 + 1], hA23);
                a3 = fma2(a3, Wr[3][2 * c8],     hA01);
                a3 = fma2(a3, Wr[3][2 * c8 + 1], hA23);
                b0 = fma2(b0, Wr[0][2 * c8],     hB01);
                b0 = fma2(b0, Wr[0][2 * c8 + 1], hB23);
                b1 = fma2(b1, Wr[1][2 * c8],     hB01);
                b1 = fma2(b1, Wr[1][2 * c8 + 1], hB23);
                b2 = fma2(b2, Wr[2][2 * c8],     hB01);
                b2 = fma2(b2, Wr[2][2 * c8 + 1], hB23);
                b3 = fma2(b3, Wr[3][2 * c8],     hB01);
                b3 = fma2(b3, Wr[3][2 * c8 + 1], hB23);
            }
#pragma unroll
            for (int m = 1; m < 8; m <<= 1) {
                a0 = add2(a0, shfl_xor2(a0, m));
                a1 = add2(a1, shfl_xor2(a1, m));
                a2 = add2(a2, shfl_xor2(a2, m));
                a3 = add2(a3, shfl_xor2(a3, m));
                b0 = add2(b0, shfl_xor2(b0, m));
                b1 = add2(b1, shfl_xor2(b1, m));
                b2 = add2(b2, shfl_xor2(b2, m));
                b3 = add2(b3, shfl_xor2(b3, m));
            }
            if (kq == 0) {
                const int rb = warp * 16 + rq;
                gates_sm[bp][rb]          = a0.x + a0.y;
                gates_sm[bp][rb + 4]      = a1.x + a1.y;
                gates_sm[bp][rb + 8]      = a2.x + a2.y;
                gates_sm[bp][rb + 12]     = a3.x + a3.y;
                gates_sm[bp + 1][rb]      = b0.x + b0.y;
                gates_sm[bp + 1][rb + 4]  = b1.x + b1.y;
                gates_sm[bp + 1][rb + 8]  = b2.x + b2.y;
                gates_sm[bp + 1][rb + 12] = b3.x + b3.y;
            }
        }
        __syncthreads();

        // ---- cell update: thread owns (batch=b_loc, col=ccol) ----
        {
            const float gi = gates_sm[b_loc][ccol]      + xg[0];
            const float gf = gates_sm[b_loc][32 + ccol] + xg[1];
            const float gc = gates_sm[b_loc][64 + ccol] + xg[2];
            const float go = gates_sm[b_loc][96 + ccol] + xg[3];
            const float i_ = sigmoidf_(gi);
            const float f_ = sigmoidf_(gf);
            const float z_ = tanhf(gc);
            const float o_ = sigmoidf_(go);
            cstate = f_ * cstate + i_ * z_;
            const float hv = o_ * tanhf(cstate);
            g_hbuf[(size_t)((t + 1) & 1) * (BATCH * VD) + b_glob * VD + cgrp * 32 + ccol] = hv;
            __stcs(HS + ((size_t)b_glob * SEQT + t) * VD + cgrp * 32 + ccol, hv);

            if (t + 1 < SEQT) {
#pragma unroll
                for (int g = 0; g < 4; ++g)
                    xg[g] = __ldcs(g_xp + ((((size_t)(t + 1) * 8 + cgrp) * 4 + g) * 128 + b_glob) * 32 + ccol);
            }
        }

        // ---- per-group flag barrier ----
        const unsigned target = gen0 + (unsigned)(t + 1);
        __syncthreads();
        if (tid == 0) exch_release(&g_flag[bgrp * 32 + cgrp], target);
        if (lane < 8) {
            const unsigned* f = &g_flag[bgrp * 32 + lane];
            while ((int)(ld_acq(f) - target) < 0) { }
        }
        __syncwarp();
    }
}

// ---------------- fc weight row-normalization (1 warp per row) ----------------
__global__ void __launch_bounds__(32)
norm_fc(const float* __restrict__ w) {
    const int o = blockIdx.x;
    const int lane = threadIdx.x;
    float4 v0 = *(const float4*)(w + o * VD + lane * 8);
    float4 v1 = *(const float4*)(w + o * VD + lane * 8 + 4);
    float s = v0.x * v0.x + v0.y * v0.y + v0.z * v0.z + v0.w * v0.w
            + v1.x * v1.x + v1.y * v1.y + v1.z * v1.z + v1.w * v1.w;
#pragma unroll
    for (int m = 16; m > 0; m >>= 1) s += __shfl_xor_sync(0xffffffffu, s, m);
    const float inv = rsqrtf(s);
    float4 o0 = make_float4(v0.x * inv, v0.y * inv, v0.z * inv, v0.w * inv);
    float4 o1 = make_float4(v1.x * inv, v1.y * inv, v1.z * inv, v1.w * inv);
    *(float4*)(g_wn + o * VD + lane * 8)     = o0;
    *(float4*)(g_wn + o * VD + lane * 8 + 4) = o1;
}

// ---------------- final FC: out[M,256] = h2s[M,256] @ wn^T + b (f32x2) ----------------
__global__ void __launch_bounds__(256)
fc_kernel(const float* __restrict__ fc_b, float* __restrict__ out) {
    __shared__ float As[16][68];
    __shared__ float Bs[16][68];
    const int tid = threadIdx.x;
    const int bm = blockIdx.x * 64;
    const int bn = blockIdx.y * 64;
    const int tx = tid & 15;
    const int ty = tid >> 4;
    const int lr = tid >> 2;
    const int lc = (tid & 3) * 4;

    float2 acc[4][2];
#pragma unroll
    for (int i = 0; i < 4; ++i) {
        acc[i][0] = make_float2(0.f, 0.f);
        acc[i][1] = make_float2(0.f, 0.f);
    }

    for (int k0 = 0; k0 < VD; k0 += 16) {
        float4 a4 = *(const float4*)(g_h2s + ((size_t)(bm + lr)) * VD + k0 + lc);
        float4 b4 = *(const float4*)(g_wn + (bn + lr) * VD + k0 + lc);
        As[lc + 0][lr] = a4.x; As[lc + 1][lr] = a4.y;
        As[lc + 2][lr] = a4.z; As[lc + 3][lr] = a4.w;
        Bs[lc + 0][lr] = b4.x; Bs[lc + 1][lr] = b4.y;
        Bs[lc + 2][lr] = b4.z; Bs[lc + 3][lr] = b4.w;
        __syncthreads();
#pragma unroll
        for (int kk = 0; kk < 16; ++kk) {
            const float4 av = *(const float4*)&As[kk][ty * 4];
            const float4 bv = *(const float4*)&Bs[kk][tx * 4];
            float2 bp0 = make_float2(bv.x, bv.y);
            float2 bp1 = make_float2(bv.z, bv.w);
            float a[4] = {av.x, av.y, av.z, av.w};
#pragma unroll
            for (int i = 0; i < 4; ++i) {
                float2 ap = make_float2(a[i], a[i]);
                acc[i][0] = fma2(acc[i][0], ap, bp0);
                acc[i][1] = fma2(acc[i][1], ap, bp1);
            }
        }
        __syncthreads();
    }

    float4 fb = *(const float4*)(fc_b + bn + tx * 4);
#pragma unroll
    for (int i = 0; i < 4; ++i) {
        const size_t row = (size_t)(bm + ty * 4 + i) * VD + bn + tx * 4;
        float4 o;
        o.x = acc[i][0].x + fb.x;
        o.y = acc[i][0].y + fb.y;
        o.z = acc[i][1].x + fb.z;
        o.w = acc[i][1].y + fb.w;
        *(float4*)(out + row) = o;
    }
}

// ---------------- launch ----------------
extern "C" void kernel_launch(void* const* d_in, const int* in_sizes, int n_in,
                              void* d_out, int out_size) {
    (void)in_sizes; (void)n_in; (void)out_size;
    const float* x    = (const float*)d_in[0];
    const float* Wih1 = (const float*)d_in[1];
    const float* Whh1 = (const float*)d_in[2];
    const float* bih1 = (const float*)d_in[3];
    const float* bhh1 = (const float*)d_in[4];
    const float* Wih2 = (const float*)d_in[5];
    const float* Whh2 = (const float*)d_in[6];
    const float* bih2 = (const float*)d_in[7];
    const float* bhh2 = (const float*)d_in[8];
    const float* fcw  = (const float*)d_in[9];
    const float* fcb  = (const float*)d_in[10];
    float* out = (float*)d_out;

    float* h1s_ptr = nullptr;
    cudaGetSymbolAddress((void**)&h1s_ptr, g_h1s);

    norm_fc<<<256, 32>>>(fcw);
    dim3 ggrid(1024, 8);
    gemm_xproj<<<ggrid, 256>>>(x, Wih1, bih1, bhh1);
    lstm_rec<<<128, TPB>>>(Whh1, 0);
    gemm_xproj<<<ggrid, 256>>>(h1s_ptr, Wih2, bih2, bhh2);
    lstm_rec<<<128, TPB>>>(Whh2, 1);
    dim3 fgrid(BATCH * SEQT / 64, VD / 64);
    fc_kernel<<<fgrid, 256>>>(fcb, out);
}

// round 13
// speedup vs baseline: 2.0381x; 1.0972x over previous
#include <cuda_runtime.h>
#include <cstdint>
#include <cstddef>

#define BATCH 128
#define SEQT  1024
#define VD    256
#define TPB   256

// ---------------- device scratch (static, no allocation) ----------------
__device__ float g_xp[134217728];                       // x_proj permuted [T][cg8][g4][b128][col32]
__device__ float g_h1s[BATCH * SEQT * VD];              // layer-1 hidden states [B,T,V]
__device__ float g_h2s[BATCH * SEQT * VD];              // layer-2 hidden states [B,T,V]
__device__ __align__(128) float g_hbuf[2 * BATCH * VD]; // double-buffered h exchange
__device__ float g_wn[VD * VD];                         // row-normalized fc weight
// per-group flag barrier: 16 groups x 8 CTA flags (first 32B of a 128B line)
__device__ __align__(128) unsigned g_flag[16 * 32];

// ---------------- packed f32x2 helpers ----------------
__device__ __forceinline__ float2 fma2(float2 acc, float2 w, float2 v) {
    unsigned long long ua, uw, uv;
    ua = *reinterpret_cast<unsigned long long*>(&acc);
    uw = *reinterpret_cast<unsigned long long*>(&w);
    uv = *reinterpret_cast<unsigned long long*>(&v);
    asm("fma.rn.f32x2 %0, %1, %2, %0;" : "+l"(ua) : "l"(uw), "l"(uv));
    return *reinterpret_cast<float2*>(&ua);
}

__device__ __forceinline__ float sigmoidf_(float x) {
    return 1.0f / (1.0f + __expf(-x));
}

// scalar 8-lane butterfly over lane bits 0..2 (kq); result valid on kq==0
__device__ __forceinline__ float red8(float2 a) {
    float s = a.x + a.y;
    s += __shfl_xor_sync(0xffffffffu, s, 1);
    s += __shfl_xor_sync(0xffffffffu, s, 2);
    s += __shfl_xor_sync(0xffffffffu, s, 4);
    return s;
}

__device__ __forceinline__ unsigned ld_acq(const unsigned* p) {
    unsigned v;
    asm volatile("ld.acquire.gpu.global.u32 %0, [%1];" : "=r"(v) : "l"(p) : "memory");
    return v;
}

__device__ __forceinline__ void exch_release(unsigned* p, unsigned v) {
    unsigned d;
    asm volatile("atom.release.gpu.global.exch.b32 %0, [%1], %2;"
                 : "=r"(d) : "l"(p), "r"(v) : "memory");
}

// =======================================================================
// GEMM: x_proj[m][n] = A[m][0:256] . W[n][0:256] + bih[n] + bhh[n]
// (unchanged from R12: BM128/BN128/BK8, TM8/TN8, cumulative B stagger)
// =======================================================================
#define GBK 8

__global__ void __launch_bounds__(256)
gemm_xproj(const float* __restrict__ A, const float* __restrict__ W,
           const float* __restrict__ bih, const float* __restrict__ bhh) {
    __shared__ float As[2][GBK][132];
    __shared__ float Bs[2][GBK][144];

    const int tid = threadIdx.x;
    const int m0 = blockIdx.x * 128;   // gridDim.x = 1024
    const int n0 = blockIdx.y * 128;   // gridDim.y = 8
    const int tx = tid & 15;           // n subtile (8 cols)
    const int ty = tid >> 4;           // m subtile (8 rows)

    const int lr = tid >> 1;           // 0..127 (tile row for loads)
    const int lc = (tid & 1) * 4;      // k offset 0 or 4
    const int bsh = 4 * (lr >> 5);     // cumulative B stagger at store
    const int rsh = 4 * (tx >> 2);     // cumulative B stagger at read

    const float* Aptr = A + (size_t)(m0 + lr) * 256 + lc;
    const float* Wptr = W + (size_t)(n0 + lr) * 256 + lc;

    float2 acc[8][4];
#pragma unroll
    for (int i = 0; i < 8; ++i)
#pragma unroll
        for (int j = 0; j < 4; ++j) acc[i][j] = make_float2(0.f, 0.f);

    float4 la = *(const float4*)(Aptr);
    float4 lb = *(const float4*)(Wptr);
#pragma unroll
    for (int i = 0; i < 4; ++i) {
        As[0][lc + i][lr]       = (&la.x)[i];
        Bs[0][lc + i][lr + bsh] = (&lb.x)[i];
    }
    __syncthreads();

    for (int kt = 0; kt < 32; ++kt) {
        const int buf = kt & 1;
        if (kt < 31) {
            la = *(const float4*)(Aptr + (kt + 1) * 8);
            lb = *(const float4*)(Wptr + (kt + 1) * 8);
        }
#pragma unroll
        for (int kk = 0; kk < GBK; ++kk) {
            float4 a0 = *(const float4*)&As[buf][kk][ty * 8];
            float4 a1 = *(const float4*)&As[buf][kk][ty * 8 + 4];
            float4 b0 = *(const float4*)&Bs[buf][kk][tx * 8 + rsh];
            float4 b1 = *(const float4*)&Bs[buf][kk][tx * 8 + 4 + rsh];
            float2 bp[4];
            bp[0] = make_float2(b0.x, b0.y);
            bp[1] = make_float2(b0.z, b0.w);
            bp[2] = make_float2(b1.x, b1.y);
            bp[3] = make_float2(b1.z, b1.w);
            float av[8] = {a0.x, a0.y, a0.z, a0.w, a1.x, a1.y, a1.z, a1.w};
#pragma unroll
            for (int mi = 0; mi < 8; ++mi) {
                float2 ap = make_float2(av[mi], av[mi]);
                acc[mi][0] = fma2(acc[mi][0], ap, bp[0]);
                acc[mi][1] = fma2(acc[mi][1], ap, bp[1]);
                acc[mi][2] = fma2(acc[mi][2], ap, bp[2]);
                acc[mi][3] = fma2(acc[mi][3], ap, bp[3]);
            }
        }
        if (kt < 31) {
            const int nb = buf ^ 1;
#pragma unroll
            for (int i = 0; i < 4; ++i) {
                As[nb][lc + i][lr]       = (&la.x)[i];
                Bs[nb][lc + i][lr + bsh] = (&lb.x)[i];
            }
        }
        __syncthreads();
    }

    // epilogue: bias + permuted store (2x STG.128 per mi)
    const int n = n0 + tx * 8;
    float4 bi0 = *(const float4*)(bih + n);
    float4 bh0 = *(const float4*)(bhh + n);
    float4 bi1 = *(const float4*)(bih + n + 4);
    float4 bh1 = *(const float4*)(bhh + n + 4);
    float4 ba = make_float4(bi0.x + bh0.x, bi0.y + bh0.y, bi0.z + bh0.z, bi0.w + bh0.w);
    float4 bb4 = make_float4(bi1.x + bh1.x, bi1.y + bh1.y, bi1.z + bh1.z, bi1.w + bh1.w);

    const int g      = n >> 8;
    const int col256 = n & 255;
    const int cg     = col256 >> 5;
    const int j0     = col256 & 31;     // in {0,8,16,24}
    const int bb     = m0 >> 10;
    const int t0     = (m0 & 1023) + ty * 8;
#pragma unroll
    for (int mi = 0; mi < 8; ++mi) {
        float4 o0, o1;
        o0.x = acc[mi][0].x + ba.x;
        o0.y = acc[mi][0].y + ba.y;
        o0.z = acc[mi][1].x + ba.z;
        o0.w = acc[mi][1].y + ba.w;
        o1.x = acc[mi][2].x + bb4.x;
        o1.y = acc[mi][2].y + bb4.y;
        o1.z = acc[mi][3].x + bb4.z;
        o1.w = acc[mi][3].y + bb4.w;
        float* dst = g_xp + ((((size_t)(t0 + mi) * 8 + cg) * 4 + g) * 128 + bb) * 32 + j0;
        *(float4*)(dst)     = o0;
        *(float4*)(dst + 4) = o1;
    }
}

// =======================================================================
// Recurrence (R12 skeleton; reduction tree switched to scalar butterfly:
// fold .x+.y first, then 3x 32-bit SHFL -- halves SHFL count per step).
// =======================================================================
__global__ void __launch_bounds__(TPB, 1)
lstm_rec(const float* __restrict__ Whh, int layer) {
    float* HS = layer ? g_h2s : g_h1s;

    const int tid  = threadIdx.x;
    const int lane = tid & 31;
    const int warp = tid >> 5;
    const int cgrp = blockIdx.x & 7;
    const int bgrp = blockIdx.x >> 3;

    const int kq = lane & 7;     // k-slice: k = kq*32 .. +31
    const int rq = lane >> 3;    // 0..3

    // 4 rows x 16 float2 weights in registers (compile-time indexed)
    float2 Wr[4][16];
#pragma unroll
    for (int i = 0; i < 4; ++i) {
        const int r = warp * 16 + rq + i * 4;
        const int Wrow = (r >> 5) * VD + cgrp * 32 + (r & 31);
        const float4* ws = (const float4*)(Whh + (size_t)Wrow * VD + kq * 32);
#pragma unroll
        for (int c8 = 0; c8 < 8; ++c8) {
            float4 w4 = ws[c8];
            Wr[i][2 * c8]     = make_float2(w4.x, w4.y);
            Wr[i][2 * c8 + 1] = make_float2(w4.z, w4.w);
        }
    }

    // cell ownership: b_loc=tid>>5 (=warp), col=tid&31
    const int b_loc  = tid >> 5;
    const int ccol   = tid & 31;
    const int b_glob = bgrp * 8 + b_loc;
    float cstate = 0.f;

    __shared__ float4 h_sm4[8 * 72];      // [8 b][8 kq-slices @ kq*9][8 f4]
    __shared__ float  gates_sm[8][128];

    const unsigned gen0 = *(volatile unsigned*)&g_flag[bgrp * 32 + cgrp];

    // prefetch x_proj for t=0
    float xg[4];
#pragma unroll
    for (int g = 0; g < 4; ++g)
        xg[g] = __ldcs(g_xp + ((((size_t)0 * 8 + cgrp) * 4 + g) * 128 + b_glob) * 32 + ccol);

    for (int t = 0; t < SEQT; ++t) {
        // ---- stage h(t-1): 512 float4, 2 per thread ----
        if (t == 0) {
            float4 z = make_float4(0.f, 0.f, 0.f, 0.f);
#pragma unroll
            for (int i = 0; i < 2; ++i) {
                const int flat = tid + i * 256;
                const int b  = flat >> 6;
                const int c4 = flat & 63;
                h_sm4[b * 72 + (c4 >> 3) * 9 + (c4 & 7)] = z;
            }
        } else {
            const float4* src = (const float4*)(g_hbuf + (size_t)(t & 1) * (BATCH * VD)) + bgrp * 512;
#pragma unroll
            for (int i = 0; i < 2; ++i) {
                const int flat = tid + i * 256;
                const int b  = flat >> 6;
                const int c4 = flat & 63;
                h_sm4[b * 72 + (c4 >> 3) * 9 + (c4 & 7)] = __ldcg(src + flat);
            }
        }
        __syncthreads();

        // ---- gates = h . Whh^T (2 batches per iteration, 8 acc chains) ----
#pragma unroll
        for (int bp = 0; bp < 8; bp += 2) {
            const float4* hrowA = h_sm4 + bp * 72 + kq * 9;
            const float4* hrowB = hrowA + 72;
            float2 a0 = make_float2(0.f, 0.f), a1 = make_float2(0.f, 0.f);
            float2 a2 = make_float2(0.f, 0.f), a3 = make_float2(0.f, 0.f);
            float2 b0 = make_float2(0.f, 0.f), b1 = make_float2(0.f, 0.f);
            float2 b2 = make_float2(0.f, 0.f), b3 = make_float2(0.f, 0.f);
#pragma unroll
            for (int c8 = 0; c8 < 8; ++c8) {
                float4 hvA = hrowA[c8];
                float4 hvB = hrowB[c8];
                float2 hA01 = make_float2(hvA.x, hvA.y);
                float2 hA23 = make_float2(hvA.z, hvA.w);
                float2 hB01 = make_float2(hvB.x, hvB.y);
                float2 hB23 = make_float2(hvB.z, hvB.w);
                a0 = fma2(a0, Wr[0][2 * c8],     hA01);
                a0 = fma2(a0, Wr[0][2 * c8 + 1], hA23);
                a1 = fma2(a1, Wr[1][2 * c8],     hA01);
                a1 = fma2(a1, Wr[1][2 * c8 + 1], hA23);
                a2 = fma2(a2, Wr[2][2 * c8],     hA01);
                a2 = fma2(a2, Wr[2][2 * c8 + 1], hA23);
                a3 = fma2(a3, Wr[3][2 * c8],     hA01);
                a3 = fma2(a3, Wr[3][2 * c8 + 1], hA23);
                b0 = fma2(b0, Wr[0][2 * c8],     hB01);
                b0 = fma2(b0, Wr[0][2 * c8 + 1], hB23);
                b1 = fma2(b1, Wr[1][2 * c8],     hB01);
                b1 = fma2(b1, Wr[1][2 * c8 + 1], hB23);
                b2 = fma2(b2, Wr[2][2 * c8],     hB01);
                b2 = fma2(b2, Wr[2][2 * c8 + 1], hB23);
                b3 = fma2(b3, Wr[3][2 * c8],     hB01);
                b3 = fma2(b3, Wr[3][2 * c8 + 1], hB23);
            }
            // scalar butterfly over the 8 kq lanes (half the SHFL count)
            const float s0 = red8(a0);
            const float s1 = red8(a1);
            const float s2 = red8(a2);
            const float s3 = red8(a3);
            const float u0 = red8(b0);
            const float u1 = red8(b1);
            const float u2 = red8(b2);
            const float u3 = red8(b3);
            if (kq == 0) {
                const int rb = warp * 16 + rq;
                gates_sm[bp][rb]          = s0;
                gates_sm[bp][rb + 4]      = s1;
                gates_sm[bp][rb + 8]      = s2;
                gates_sm[bp][rb + 12]     = s3;
                gates_sm[bp + 1][rb]      = u0;
                gates_sm[bp + 1][rb + 4]  = u1;
                gates_sm[bp + 1][rb + 8]  = u2;
                gates_sm[bp + 1][rb + 12] = u3;
            }
        }
        __syncthreads();

        // ---- cell update: thread owns (batch=b_loc, col=ccol) ----
        {
            const float gi = gates_sm[b_loc][ccol]      + xg[0];
            const float gf = gates_sm[b_loc][32 + ccol] + xg[1];
            const float gc = gates_sm[b_loc][64 + ccol] + xg[2];
            const float go = gates_sm[b_loc][96 + ccol] + xg[3];
            const float i_ = sigmoidf_(gi);
            const float f_ = sigmoidf_(gf);
            const float z_ = tanhf(gc);
            const float o_ = sigmoidf_(go);
            cstate = f_ * cstate + i_ * z_;
            const float hv = o_ * tanhf(cstate);
            g_hbuf[(size_t)((t + 1) & 1) * (BATCH * VD) + b_glob * VD + cgrp * 32 + ccol] = hv;
            __stcs(HS + ((size_t)b_glob * SEQT + t) * VD + cgrp * 32 + ccol, hv);

            if (t + 1 < SEQT) {
#pragma unroll
                for (int g = 0; g < 4; ++g)
                    xg[g] = __ldcs(g_xp + ((((size_t)(t + 1) * 8 + cgrp) * 4 + g) * 128 + b_glob) * 32 + ccol);
            }
        }

        // ---- per-group flag barrier ----
        const unsigned target = gen0 + (unsigned)(t + 1);
        __syncthreads();
        if (tid == 0) exch_release(&g_flag[bgrp * 32 + cgrp], target);
        if (lane < 8) {
            const unsigned* f = &g_flag[bgrp * 32 + lane];
            while ((int)(ld_acq(f) - target) < 0) { }
        }
        __syncwarp();
    }
}

// ---------------- fc weight row-normalization (1 warp per row) ----------------
__global__ void __launch_bounds__(32)
norm_fc(const float* __restrict__ w) {
    const int o = blockIdx.x;
    const int lane = threadIdx.x;
    float4 v0 = *(const float4*)(w + o * VD + lane * 8);
    float4 v1 = *(const float4*)(w + o * VD + lane * 8 + 4);
    float s = v0.x * v0.x + v0.y * v0.y + v0.z * v0.z + v0.w * v0.w
            + v1.x * v1.x + v1.y * v1.y + v1.z * v1.z + v1.w * v1.w;
#pragma unroll
    for (int m = 16; m > 0; m >>= 1) s += __shfl_xor_sync(0xffffffffu, s, m);
    const float inv = rsqrtf(s);
    float4 o0 = make_float4(v0.x * inv, v0.y * inv, v0.z * inv, v0.w * inv);
    float4 o1 = make_float4(v1.x * inv, v1.y * inv, v1.z * inv, v1.w * inv);
    *(float4*)(g_wn + o * VD + lane * 8)     = o0;
    *(float4*)(g_wn + o * VD + lane * 8 + 4) = o1;
}

// ---------------- final FC: out[M,256] = h2s[M,256] @ wn^T + b (f32x2) ----------------
__global__ void __launch_bounds__(256)
fc_kernel(const float* __restrict__ fc_b, float* __restrict__ out) {
    __shared__ float As[16][68];
    __shared__ float Bs[16][68];
    const int tid = threadIdx.x;
    const int bm = blockIdx.x * 64;
    const int bn = blockIdx.y * 64;
    const int tx = tid & 15;
    const int ty = tid >> 4;
    const int lr = tid >> 2;
    const int lc = (tid & 3) * 4;

    float2 acc[4][2];
#pragma unroll
    for (int i = 0; i < 4; ++i) {
        acc[i][0] = make_float2(0.f, 0.f);
        acc[i][1] = make_float2(0.f, 0.f);
    }

    for (int k0 = 0; k0 < VD; k0 += 16) {
        float4 a4 = *(const float4*)(g_h2s + ((size_t)(bm + lr)) * VD + k0 + lc);
        float4 b4 = *(const float4*)(g_wn + (bn + lr) * VD + k0 + lc);
        As[lc + 0][lr] = a4.x; As[lc + 1][lr] = a4.y;
        As[lc + 2][lr] = a4.z; As[lc + 3][lr] = a4.w;
        Bs[lc + 0][lr] = b4.x; Bs[lc + 1][lr] = b4.y;
        Bs[lc + 2][lr] = b4.z; Bs[lc + 3][lr] = b4.w;
        __syncthreads();
#pragma unroll
        for (int kk = 0; kk < 16; ++kk) {
            const float4 av = *(const float4*)&As[kk][ty * 4];
            const float4 bv = *(const float4*)&Bs[kk][tx * 4];
            float2 bp0 = make_float2(bv.x, bv.y);
            float2 bp1 = make_float2(bv.z, bv.w);
            float a[4] = {av.x, av.y, av.z, av.w};
#pragma unroll
            for (int i = 0; i < 4; ++i) {
                float2 ap = make_float2(a[i], a[i]);
                acc[i][0] = fma2(acc[i][0], ap, bp0);
                acc[i][1] = fma2(acc[i][1], ap, bp1);
            }
        }
        __syncthreads();
    }

    float4 fb = *(const float4*)(fc_b + bn + tx * 4);
#pragma unroll
    for (int i = 0; i < 4; ++i) {
        const size_t row = (size_t)(bm + ty * 4 + i) * VD + bn + tx * 4;
        float4 o;
        o.x = acc[i][0].x + fb.x;
        o.y = acc[i][0].y + fb.y;
        o.z = acc[i][1].x + fb.z;
        o.w = acc[i][1].y + fb.w;
        *(float4*)(out + row) = o;
    }
}

// ---------------- launch ----------------
extern "C" void kernel_launch(void* const* d_in, const int* in_sizes, int n_in,
                              void* d_out, int out_size) {
    (void)in_sizes; (void)n_in; (void)out_size;
    const float* x    = (const float*)d_in[0];
    const float* Wih1 = (const float*)d_in[1];
    const float* Whh1 = (const float*)d_in[2];
    const float* bih1 = (const float*)d_in[3];
    const float* bhh1 = (const float*)d_in[4];
    const float* Wih2 = (const float*)d_in[5];
    const float* Whh2 = (const float*)d_in[6];
    const float* bih2 = (const float*)d_in[7];
    const float* bhh2 = (const float*)d_in[8];
    const float* fcw  = (const float*)d_in[9];
    const float* fcb  = (const float*)d_in[10];
    float* out = (float*)d_out;

    float* h1s_ptr = nullptr;
    cudaGetSymbolAddress((void**)&h1s_ptr, g_h1s);

    norm_fc<<<256, 32>>>(fcw);
    dim3 ggrid(1024, 8);
    gemm_xproj<<<ggrid, 256>>>(x, Wih1, bih1, bhh1);
    lstm_rec<<<128, TPB>>>(Whh1, 0);
    gemm_xproj<<<ggrid, 256>>>(h1s_ptr, Wih2, bih2, bhh2);
    lstm_rec<<<128, TPB>>>(Whh2, 1);
    dim3 fgrid(BATCH * SEQT / 64, VD / 64);
    fc_kernel<<<fgrid, 256>>>(fcb, out);
}